// round 2
// baseline (speedup 1.0000x reference)
#include <cuda_runtime.h>

// Problem constants (fixed by reference setup_inputs)
#define B_TOT  16384
#define P_DIM  32
#define N_DIM  2
#define CIN    9
#define COUT   64
#define PJ     64          // P*N = BatchNorm column count
#define NPAIR  45          // upper-tri pairs of 9x9
#define NSTAT  54          // 9 (S1) + 45 (S2)
#define EPSV   1e-5f

// Scratch (device globals; no allocation allowed)
__device__ float g_stats[PJ * NSTAT];   // per-column: [0..8]=S1, [9..53]=S2 (c1<=c2)
__device__ float g_scale[PJ];
__device__ float g_shift[PJ];

// ---------------------------------------------------------------------------
// f32x2 packed helpers (Blackwell sm_103a packed fp32 pipe)
// ---------------------------------------------------------------------------
__device__ __forceinline__ unsigned long long pk2(float lo, float hi) {
    unsigned long long r;
    asm("mov.b64 %0,{%1,%2};" : "=l"(r) : "f"(lo), "f"(hi));
    return r;
}
__device__ __forceinline__ void upk2(unsigned long long v, float& lo, float& hi) {
    asm("mov.b64 {%0,%1},%2;" : "=f"(lo), "=f"(hi) : "l"(v));
}

// ---------------------------------------------------------------------------
// Kernel 0: zero the stat accumulators (graph replays re-run everything)
// ---------------------------------------------------------------------------
__global__ void k_zero() {
    int i = blockIdx.x * blockDim.x + threadIdx.x;
    if (i < PJ * NSTAT) g_stats[i] = 0.0f;
}

// ---------------------------------------------------------------------------
// Kernel 1: accumulate S1[j][c] = sum_b p, S2[j][c1c2] = sum_b p*p
// 256 blocks x 256 threads. thread -> (j = tid&63, b-group = tid>>6)
// Each thread walks 16 b values, reduces in registers, then smem, then
// global atomics (256 blocks x 3456 floats -> cheap).
// ---------------------------------------------------------------------------
__global__ __launch_bounds__(256) void k_stats(const float* __restrict__ pil) {
    __shared__ float sred[PJ * NSTAT];
    const int tid = threadIdx.x;
    for (int i = tid; i < PJ * NSTAT; i += 256) sred[i] = 0.0f;
    __syncthreads();

    const int j = tid & 63;
    const int g = tid >> 6;   // 0..3

    float s1[CIN];
    float s2[NPAIR];
#pragma unroll
    for (int k = 0; k < CIN; k++) s1[k] = 0.0f;
#pragma unroll
    for (int k = 0; k < NPAIR; k++) s2[k] = 0.0f;

    for (int sweep = 0; sweep < 16; sweep++) {
        const int b = sweep * 1024 + blockIdx.x * 4 + g;
        const float* p = pil + (size_t)b * (PJ * CIN) + j * CIN;
        float v[CIN];
#pragma unroll
        for (int k = 0; k < CIN; k++) v[k] = p[k];
        int idx = 0;
#pragma unroll
        for (int c1 = 0; c1 < CIN; c1++) {
            s1[c1] += v[c1];
#pragma unroll
            for (int c2 = c1; c2 < CIN; c2++) { s2[idx] += v[c1] * v[c2]; idx++; }
        }
    }

    float* dstj = sred + j * NSTAT;
#pragma unroll
    for (int k = 0; k < CIN; k++) atomicAdd(&dstj[k], s1[k]);
#pragma unroll
    for (int k = 0; k < NPAIR; k++) atomicAdd(&dstj[CIN + k], s2[k]);
    __syncthreads();

    for (int i = tid; i < PJ * NSTAT; i += 256) atomicAdd(&g_stats[i], sred[i]);
}

// ---------------------------------------------------------------------------
// Kernel 2: finalize -> per-column scale/shift
// mean[j]  = (S1[j] . Wsum) / (B*64)
// E[x^2]   = (sum_{c1<=c2} S2 * G * (2 - [c1==c2])) / (B*64),  G = W^T W
// scale[j] = gamma[j] * rsqrt(var + eps);  shift[j] = beta[j] - mean*scale
// ---------------------------------------------------------------------------
__global__ void k_finalize(const float* __restrict__ W,
                           const float* __restrict__ gamma,
                           const float* __restrict__ beta) {
    const int j = threadIdx.x;  // 64 threads
    float wsum[CIN];
    float G[NPAIR];
#pragma unroll
    for (int k = 0; k < CIN; k++) wsum[k] = 0.0f;
#pragma unroll
    for (int k = 0; k < NPAIR; k++) G[k] = 0.0f;

    for (int o = 0; o < COUT; o++) {
        float w[CIN];
#pragma unroll
        for (int k = 0; k < CIN; k++) w[k] = W[o * CIN + k];
        int idx = 0;
#pragma unroll
        for (int c1 = 0; c1 < CIN; c1++) {
            wsum[c1] += w[c1];
#pragma unroll
            for (int c2 = c1; c2 < CIN; c2++) { G[idx] += w[c1] * w[c2]; idx++; }
        }
    }

    const float* st = g_stats + j * NSTAT;
    const float inv = 1.0f / ((float)B_TOT * (float)COUT);

    float mean = 0.0f;
#pragma unroll
    for (int k = 0; k < CIN; k++) mean += st[k] * wsum[k];
    mean *= inv;

    float ex2 = 0.0f;
    int idx = 0;
#pragma unroll
    for (int c1 = 0; c1 < CIN; c1++) {
#pragma unroll
        for (int c2 = c1; c2 < CIN; c2++) {
            const float m = (c1 == c2) ? 1.0f : 2.0f;
            ex2 += st[CIN + idx] * G[idx] * m;
            idx++;
        }
    }
    ex2 *= inv;

    const float var = ex2 - mean * mean;
    const float sc = gamma[j] * rsqrtf(var + EPSV);
    g_scale[j] = sc;
    g_shift[j] = beta[j] - mean * sc;
}

// ---------------------------------------------------------------------------
// Kernel 3: main pass. One warp per b, lane = p.
// Packed f32x2: both n-values processed per FFMA2; weights pre-duplicated
// {w,w} in shared. Coalesced 128B stores per (c) step.
// ---------------------------------------------------------------------------
__global__ __launch_bounds__(256) void k_main(const float* __restrict__ pil,
                                              const float* __restrict__ W,
                                              float* __restrict__ out) {
    __shared__ unsigned long long sW2[COUT * CIN];   // {w,w} pairs, 4.5 KB
    const int tid = threadIdx.x;
    for (int i = tid; i < COUT * CIN; i += 256) {
        const float w = W[i];
        sW2[i] = pk2(w, w);
    }
    __syncthreads();

    const int warp = tid >> 5;
    const int lane = tid & 31;
    const int b = blockIdx.x * 8 + warp;

    // Load this lane's pillar slice: 18 floats = (n=0)[0..8], (n=1)[0..8]
    const float* p = pil + (size_t)b * (PJ * CIN) + lane * (N_DIM * CIN);
    unsigned long long pv[CIN];
#pragma unroll
    for (int k = 0; k < CIN; k++) pv[k] = pk2(p[k], p[CIN + k]);

    // Per-lane BN constants for columns j0 = 2*lane, j1 = 2*lane+1
    const unsigned long long scv = pk2(g_scale[2 * lane], g_scale[2 * lane + 1]);
    const unsigned long long shv = pk2(g_shift[2 * lane], g_shift[2 * lane + 1]);

    float* ob = out + (size_t)b * (COUT * P_DIM) + lane;

#pragma unroll 4
    for (int c = 0; c < COUT; c++) {
        unsigned long long acc = 0ull;   // {0.0f, 0.0f}
        const unsigned long long* wr = sW2 + c * CIN;
#pragma unroll
        for (int k = 0; k < CIN; k++) {
            asm("fma.rn.f32x2 %0,%1,%2,%0;" : "+l"(acc) : "l"(pv[k]), "l"(wr[k]));
        }
        unsigned long long y;
        asm("fma.rn.f32x2 %0,%1,%2,%3;" : "=l"(y) : "l"(acc), "l"(scv), "l"(shv));
        float y0, y1;
        upk2(y, y0, y1);
        ob[c * P_DIM] = fmaxf(fmaxf(y0, y1), 0.0f);
    }
}

// ---------------------------------------------------------------------------
extern "C" void kernel_launch(void* const* d_in, const int* in_sizes, int n_in,
                              void* d_out, int out_size) {
    const float* pillars = (const float*)d_in[0];
    // d_in[1] = num_points_per_pillar (unused by the reference computation)
    const float* W       = (const float*)d_in[2];
    const float* gamma   = (const float*)d_in[3];
    const float* beta    = (const float*)d_in[4];
    float* out           = (float*)d_out;

    k_zero<<<(PJ * NSTAT + 255) / 256, 256>>>();
    k_stats<<<256, 256>>>(pillars);
    k_finalize<<<1, PJ>>>(W, gamma, beta);
    k_main<<<B_TOT / 8, 256>>>(pillars, W, out);
}

// round 3
// speedup vs baseline: 1.1784x; 1.1784x over previous
#include <cuda_runtime.h>

// Problem constants (fixed by reference setup_inputs)
#define B_TOT  16384
#define P_DIM  32
#define N_DIM  2
#define CIN    9
#define COUT   64
#define PJ     64          // P*N = BatchNorm column count
#define NPAIR  45          // upper-tri pairs of 9x9
#define NSTAT  54          // 9 (S1) + 45 (S2)
#define NSLC   8           // accumulator slices (atomic contention relief)
#define EPSV   1e-5f

typedef unsigned long long ull;

// Scratch (device globals; no allocation allowed)
__device__ float g_part[NSLC][PJ * NSTAT];
__device__ float g_scale[PJ];
__device__ float g_shift[PJ];

// ---------------------------------------------------------------------------
// f32x2 packed helpers (Blackwell sm_103a packed fp32 pipe)
// ---------------------------------------------------------------------------
__device__ __forceinline__ ull pk2(float lo, float hi) {
    ull r;
    asm("mov.b64 %0,{%1,%2};" : "=l"(r) : "f"(lo), "f"(hi));
    return r;
}
__device__ __forceinline__ void upk2(ull v, float& lo, float& hi) {
    asm("mov.b64 {%0,%1},%2;" : "=f"(lo), "=f"(hi) : "l"(v));
}

// ---------------------------------------------------------------------------
// Kernel 0: zero the sliced stat accumulators (graph replays re-run all)
// ---------------------------------------------------------------------------
__global__ void k_zero() {
    int i = blockIdx.x * blockDim.x + threadIdx.x;
    if (i < NSLC * PJ * NSTAT) ((float*)g_part)[i] = 0.0f;
}

// ---------------------------------------------------------------------------
// Kernel 1: accumulate S1[j][c] = sum_b p,  S2[j][c1c2] = sum_b p*p.
// 512 blocks x 256 threads, 8 sweeps. Per sweep each block stages 4
// CONTIGUOUS pillar rows (9216 B) via coalesced float4 loads, then thread
// (j = tid&63, g = tid>>6) consumes row g / column j from smem
// (stride-9-word reads: gcd(9,32)=1 -> conflict-free).
// ---------------------------------------------------------------------------
__global__ __launch_bounds__(256) void k_stats(const float* __restrict__ pil) {
    __shared__ float4 st4[576];             // 4 rows x 576 floats
    __shared__ float sred[PJ * NSTAT];
    const int tid = threadIdx.x;
    const int j = tid & 63;
    const int g = tid >> 6;                 // 0..3 (uniform within a warp)

    float s1[CIN];
    float s2[NPAIR];
#pragma unroll
    for (int k = 0; k < CIN; k++) s1[k] = 0.0f;
#pragma unroll
    for (int k = 0; k < NPAIR; k++) s2[k] = 0.0f;

    for (int sweep = 0; sweep < 8; sweep++) {
        const int b0 = sweep * 2048 + blockIdx.x * 4;
        const float4* src = (const float4*)(pil + (size_t)b0 * 576);
        __syncthreads();                    // protect st4 reuse
#pragma unroll
        for (int i = tid; i < 576; i += 256) st4[i] = src[i];
        __syncthreads();

        const float* v = (const float*)st4 + g * 576 + j * CIN;
        float vv[CIN];
#pragma unroll
        for (int k = 0; k < CIN; k++) vv[k] = v[k];
        int idx = 0;
#pragma unroll
        for (int c1 = 0; c1 < CIN; c1++) {
            s1[c1] += vv[c1];
#pragma unroll
            for (int c2 = c1; c2 < CIN; c2++) { s2[idx] += vv[c1] * vv[c2]; idx++; }
        }
    }

    // Block-level reduction across the 4 g-groups, then sliced global atomics.
    for (int i = tid; i < PJ * NSTAT; i += 256) sred[i] = 0.0f;
    __syncthreads();
    float* dj = sred + j * NSTAT;
#pragma unroll
    for (int k = 0; k < CIN; k++) atomicAdd(&dj[k], s1[k]);
#pragma unroll
    for (int k = 0; k < NPAIR; k++) atomicAdd(&dj[CIN + k], s2[k]);
    __syncthreads();

    float* gp = g_part[blockIdx.x & (NSLC - 1)];
    for (int i = tid; i < PJ * NSTAT; i += 256) atomicAdd(&gp[i], sred[i]);
}

// ---------------------------------------------------------------------------
// Kernel 2: finalize -> per-column scale/shift.
// Phase 1 (cooperative): thread t<45 computes Gram pair G[t] = sum_o w w';
//                        t in [45,54) computes column sums of W.
// Phase 2: thread j reduces the NSLC slices and forms scale/shift.
// ---------------------------------------------------------------------------
__global__ void k_finalize(const float* __restrict__ W,
                           const float* __restrict__ gamma,
                           const float* __restrict__ beta) {
    __shared__ float sG[NPAIR];
    __shared__ float swsum[CIN];
    const int t = threadIdx.x;              // 64 threads

    if (t < NPAIR) {
        int c1 = 0, c2 = 0, idx = 0;
#pragma unroll
        for (int a = 0; a < CIN; a++)
#pragma unroll
            for (int b2 = a; b2 < CIN; b2++) {
                if (idx == t) { c1 = a; c2 = b2; }
                idx++;
            }
        float s = 0.0f;
        for (int o = 0; o < COUT; o++) s += W[o * CIN + c1] * W[o * CIN + c2];
        sG[t] = s;
    } else if (t < NSTAT) {
        const int c = t - NPAIR;
        float s = 0.0f;
        for (int o = 0; o < COUT; o++) s += W[o * CIN + c];
        swsum[c] = s;
    }
    __syncthreads();

    const int j = t;
    float st[NSTAT];
#pragma unroll
    for (int k = 0; k < NSTAT; k++) {
        float s = 0.0f;
#pragma unroll
        for (int sl = 0; sl < NSLC; sl++) s += g_part[sl][j * NSTAT + k];
        st[k] = s;
    }

    const float inv = 1.0f / ((float)B_TOT * (float)COUT);
    float mean = 0.0f;
#pragma unroll
    for (int k = 0; k < CIN; k++) mean += st[k] * swsum[k];
    mean *= inv;

    float ex2 = 0.0f;
    int idx = 0;
#pragma unroll
    for (int c1 = 0; c1 < CIN; c1++)
#pragma unroll
        for (int c2 = c1; c2 < CIN; c2++) {
            const float m = (c1 == c2) ? 1.0f : 2.0f;
            ex2 += st[CIN + idx] * sG[idx] * m;
            idx++;
        }
    ex2 *= inv;

    const float var = ex2 - mean * mean;
    const float sc = gamma[j] * rsqrtf(var + EPSV);
    g_scale[j] = sc;
    g_shift[j] = beta[j] - mean * sc;
}

// ---------------------------------------------------------------------------
// Kernel 3: main pass. One warp per b, lane = p.
//  - Pillar row staged through shared via coalesced float4 (18 wavefronts
//    instead of 324 strided-scalar ones).
//  - f32x2 vectorized over CHANNEL PAIRS: one LDS.64 of {W[c],W[c+1]} feeds
//    two FFMA2s (n=0 and n=1) -> weight LDS halved to 288 per warp-b.
//  - BN folds per column j=2p+n (same j for both packed channels).
//  - Coalesced 128B STG.32 per channel.
// ---------------------------------------------------------------------------
__global__ __launch_bounds__(256, 3) void k_main(const float* __restrict__ pil,
                                                 const float* __restrict__ W,
                                                 float* __restrict__ out) {
    __shared__ ull sW2[(COUT / 2) * CIN];       // {W[c][k], W[c+1][k]}, 2.25 KB
    __shared__ float spill[8][576];             // per-warp pillar row, 18 KB
    const int tid = threadIdx.x;

    for (int i = tid; i < (COUT / 2) * CIN; i += 256) {
        const int cp = i / CIN, k = i - cp * CIN;
        sW2[i] = pk2(W[(2 * cp) * CIN + k], W[(2 * cp + 1) * CIN + k]);
    }
    __syncthreads();

    const int warp = tid >> 5;
    const int lane = tid & 31;
    const int b = blockIdx.x * 8 + warp;

    // Coalesced stage of this warp's pillar row (576 floats = 144 float4)
    {
        const float4* src = (const float4*)(pil + (size_t)b * 576);
        float4* dst = (float4*)spill[warp];
#pragma unroll
        for (int r = 0; r < 4; r++) dst[lane + 32 * r] = src[lane + 32 * r];
        if (lane < 16) dst[128 + lane] = src[128 + lane];
    }
    __syncwarp();

    // Lane's 18 floats: n=0 -> [0..8], n=1 -> [9..17]; duplicate-pack each.
    const float* v = spill[warp] + lane * (N_DIM * CIN);
    ull pd0[CIN], pd1[CIN];
#pragma unroll
    for (int k = 0; k < CIN; k++) { const float a = v[k];       pd0[k] = pk2(a, a); }
#pragma unroll
    for (int k = 0; k < CIN; k++) { const float a = v[CIN + k]; pd1[k] = pk2(a, a); }

    const float sc0 = g_scale[2 * lane], sc1 = g_scale[2 * lane + 1];
    const float sh0 = g_shift[2 * lane], sh1 = g_shift[2 * lane + 1];
    const ull scv0 = pk2(sc0, sc0), shv0 = pk2(sh0, sh0);
    const ull scv1 = pk2(sc1, sc1), shv1 = pk2(sh1, sh1);

    float* ob = out + (size_t)b * (COUT * P_DIM) + lane;

#pragma unroll 4
    for (int cp = 0; cp < COUT / 2; cp++) {
        const ull* wr = sW2 + cp * CIN;
        ull a0 = 0ull, a1 = 0ull;
#pragma unroll
        for (int k = 0; k < CIN; k++) {
            const ull w2 = wr[k];
            asm("fma.rn.f32x2 %0,%1,%2,%0;" : "+l"(a0) : "l"(pd0[k]), "l"(w2));
            asm("fma.rn.f32x2 %0,%1,%2,%0;" : "+l"(a1) : "l"(pd1[k]), "l"(w2));
        }
        ull y0, y1;
        asm("fma.rn.f32x2 %0,%1,%2,%3;" : "=l"(y0) : "l"(a0), "l"(scv0), "l"(shv0));
        asm("fma.rn.f32x2 %0,%1,%2,%3;" : "=l"(y1) : "l"(a1), "l"(scv1), "l"(shv1));
        float y0a, y0b, y1a, y1b;
        upk2(y0, y0a, y0b);
        upk2(y1, y1a, y1b);
        ob[(2 * cp) * P_DIM]     = fmaxf(fmaxf(y0a, y1a), 0.0f);
        ob[(2 * cp + 1) * P_DIM] = fmaxf(fmaxf(y0b, y1b), 0.0f);
    }
}

// ---------------------------------------------------------------------------
extern "C" void kernel_launch(void* const* d_in, const int* in_sizes, int n_in,
                              void* d_out, int out_size) {
    const float* pillars = (const float*)d_in[0];
    // d_in[1] = num_points_per_pillar (unused by the reference computation)
    const float* W       = (const float*)d_in[2];
    const float* gamma   = (const float*)d_in[3];
    const float* beta    = (const float*)d_in[4];
    float* out           = (float*)d_out;

    k_zero<<<(NSLC * PJ * NSTAT + 255) / 256, 256>>>();
    k_stats<<<512, 256>>>(pillars);
    k_finalize<<<1, PJ>>>(W, gamma, beta);
    k_main<<<B_TOT / 8, 256>>>(pillars, W, out);
}

// round 4
// speedup vs baseline: 1.3039x; 1.1065x over previous
#include <cuda_runtime.h>

// Problem constants (fixed by reference setup_inputs)
#define B_TOT  16384
#define P_DIM  32
#define N_DIM  2
#define CIN    9
#define COUT   64
#define PJ     64          // P*N = BatchNorm column count
#define NPAIR  45          // upper-tri pairs of 9x9
#define NSTAT  54          // 9 (S1) + 45 (S2)
#define NSLC   8           // global accumulator slices
#define EPSV   1e-5f

typedef unsigned long long ull;

// Scratch (device globals; zero-initialized before first call, and k_finalize
// re-zeroes them after use so every graph replay starts from zero).
__device__ float g_part[NSLC][PJ * NSTAT];
__device__ float g_scale[PJ];
__device__ float g_shift[PJ];

// ---------------------------------------------------------------------------
// f32x2 packed helpers (Blackwell sm_103a packed fp32 pipe)
// ---------------------------------------------------------------------------
__device__ __forceinline__ ull pk2(float lo, float hi) {
    ull r;
    asm("mov.b64 %0,{%1,%2};" : "=l"(r) : "f"(lo), "f"(hi));
    return r;
}
__device__ __forceinline__ void upk2(ull v, float& lo, float& hi) {
    asm("mov.b64 {%0,%1},%2;" : "=f"(lo), "=f"(hi) : "l"(v));
}

// ---------------------------------------------------------------------------
// Kernel 1: accumulate S1[j][c] = sum_b p,  S2[j][c1c2] = sum_b p*p.
// 512 blocks x 256 threads, 4 sweeps of 8 staged rows each.
// Thread (j = tid&63, g = tid>>6) consumes rows g and g+4, column j.
// Cross-g reduction via 4 plain store/add passes (NO smem atomics),
// then coalesced global atomicAdd into one of NSLC slices.
// ---------------------------------------------------------------------------
__global__ __launch_bounds__(256) void k_stats(const float* __restrict__ pil) {
    __shared__ float4 st4[1152];            // 8 rows x 576 floats = 18.4 KB
    __shared__ float sred[PJ * NSTAT];      // 13.8 KB
    const int tid = threadIdx.x;
    const int j = tid & 63;
    const int g = tid >> 6;                 // 0..3

    float s1[CIN];
    float s2[NPAIR];
#pragma unroll
    for (int k = 0; k < CIN; k++) s1[k] = 0.0f;
#pragma unroll
    for (int k = 0; k < NPAIR; k++) s2[k] = 0.0f;

    for (int sweep = 0; sweep < 4; sweep++) {
        const int b0 = sweep * 4096 + blockIdx.x * 8;
        const float4* src = (const float4*)(pil + (size_t)b0 * 576);
        __syncthreads();                    // protect st4 reuse
#pragma unroll
        for (int r = 0; r < 4; r++) st4[tid + 256 * r] = src[tid + 256 * r];
        if (tid < 128) st4[1024 + tid] = src[1024 + tid];
        __syncthreads();

#pragma unroll
        for (int half = 0; half < 2; half++) {
            const float* v = (const float*)st4 + (g + 4 * half) * 576 + j * CIN;
            float vv[CIN];
#pragma unroll
            for (int k = 0; k < CIN; k++) vv[k] = v[k];
            int idx = 0;
#pragma unroll
            for (int c1 = 0; c1 < CIN; c1++) {
                s1[c1] += vv[c1];
#pragma unroll
                for (int c2 = c1; c2 < CIN; c2++) { s2[idx] += vv[c1] * vv[c2]; idx++; }
            }
        }
    }

    // Cross-g reduction with plain smem ops (sequential g-passes).
    __syncthreads();
#pragma unroll
    for (int gp = 0; gp < 4; gp++) {
        if (g == gp) {
            float* dj = sred + j * NSTAT;
            if (gp == 0) {
#pragma unroll
                for (int k = 0; k < CIN; k++) dj[k] = s1[k];
#pragma unroll
                for (int k = 0; k < NPAIR; k++) dj[CIN + k] = s2[k];
            } else {
#pragma unroll
                for (int k = 0; k < CIN; k++) dj[k] += s1[k];
#pragma unroll
                for (int k = 0; k < NPAIR; k++) dj[CIN + k] += s2[k];
            }
        }
        __syncthreads();
    }

    // Coalesced global accumulation (REDG, no return value).
    float* gp_ = g_part[blockIdx.x & (NSLC - 1)];
    for (int i = tid; i < PJ * NSTAT; i += 256) atomicAdd(&gp_[i], sred[i]);
}

// ---------------------------------------------------------------------------
// Kernel 2: finalize -> per-column scale/shift, then zero g_part for the
// next graph replay.
//   Phase A (coalesced): reduce NSLC slices into smem sfin[3456].
//   Phase B (cooperative): Gram pairs G[t]=sum_o w w' (t<45), col sums (t<54).
//   Phase C: thread j<64 forms scale/shift.
//   Phase D: all 256 threads zero g_part (float4).
// ---------------------------------------------------------------------------
__global__ __launch_bounds__(256) void k_finalize(const float* __restrict__ W,
                                                  const float* __restrict__ gamma,
                                                  const float* __restrict__ beta) {
    __shared__ float sfin[PJ * NSTAT];
    __shared__ float sG[NPAIR];
    __shared__ float swsum[CIN];
    const int t = threadIdx.x;

    // Phase A: coalesced slice reduction.
    for (int i = t; i < PJ * NSTAT; i += 256) {
        float s = 0.0f;
#pragma unroll
        for (int sl = 0; sl < NSLC; sl++) s += g_part[sl][i];
        sfin[i] = s;
    }

    // Phase B: Gram / column sums of W (tiny; W lives in L1 after first touch).
    if (t < NPAIR) {
        int c1 = 0, c2 = 0, idx = 0;
#pragma unroll
        for (int a = 0; a < CIN; a++)
#pragma unroll
            for (int b2 = a; b2 < CIN; b2++) {
                if (idx == t) { c1 = a; c2 = b2; }
                idx++;
            }
        float s = 0.0f;
        for (int o = 0; o < COUT; o++) s += W[o * CIN + c1] * W[o * CIN + c2];
        sG[t] = s;
    } else if (t < NSTAT) {
        const int c = t - NPAIR;
        float s = 0.0f;
        for (int o = 0; o < COUT; o++) s += W[o * CIN + c];
        swsum[c] = s;
    }
    __syncthreads();

    // Phase C: scale/shift per column j.
    if (t < PJ) {
        const int j = t;
        const float* st = sfin + j * NSTAT;
        const float inv = 1.0f / ((float)B_TOT * (float)COUT);

        float mean = 0.0f;
#pragma unroll
        for (int k = 0; k < CIN; k++) mean += st[k] * swsum[k];
        mean *= inv;

        float ex2 = 0.0f;
        int idx = 0;
#pragma unroll
        for (int c1 = 0; c1 < CIN; c1++)
#pragma unroll
            for (int c2 = c1; c2 < CIN; c2++) {
                const float m = (c1 == c2) ? 1.0f : 2.0f;
                ex2 += st[CIN + idx] * sG[idx] * m;
                idx++;
            }
        ex2 *= inv;

        const float var = ex2 - mean * mean;
        const float sc = gamma[j] * rsqrtf(var + EPSV);
        g_scale[j] = sc;
        g_shift[j] = beta[j] - mean * sc;
    }

    // Phase D: zero g_part for the next call (reads of g_part all happened
    // in Phase A, which precedes the barrier above).
    float4* gz = (float4*)g_part;
    const int nz = (NSLC * PJ * NSTAT) / 4;      // 6912 float4
    for (int i = t; i < nz; i += 256) gz[i] = make_float4(0.f, 0.f, 0.f, 0.f);
}

// ---------------------------------------------------------------------------
// Kernel 3: main pass. One warp per TWO consecutive b, lane = p.
//  - Pillar rows staged via coalesced float4 (9 LDG.128 per lane per pair).
//  - f32x2 vectorized over CHANNEL PAIRS {W[c],W[c+1]}; weight rows padded
//    to 10 ull so each cp is 5 aligned LDS.128; weights shared across both b
//    -> weight wavefronts ~80 per b (was 288).
//  - BN folded per column j=2p+n; coalesced STG.32 per channel.
// ---------------------------------------------------------------------------
__global__ __launch_bounds__(256, 2) void k_main(const float* __restrict__ pil,
                                                 const float* __restrict__ W,
                                                 float* __restrict__ out) {
    __shared__ ull sW2[(COUT / 2) * 10];        // padded {w_c,w_c+1} rows, 2.5 KB
    __shared__ float spill[8][2 * 576];         // 2 rows per warp, 36 KB
    const int tid = threadIdx.x;

    for (int i = tid; i < (COUT / 2) * 10; i += 256) {
        const int cp = i / 10, k = i - cp * 10;
        sW2[i] = (k < CIN) ? pk2(W[(2 * cp) * CIN + k], W[(2 * cp + 1) * CIN + k]) : 0ull;
    }
    __syncthreads();

    const int warp = tid >> 5;
    const int lane = tid & 31;
    const int b0 = (blockIdx.x * 8 + warp) * 2;     // this warp's two b

    // Coalesced stage of two pillar rows (1152 floats = 288 float4).
    {
        const float4* src = (const float4*)(pil + (size_t)b0 * 576);
        float4* dst = (float4*)spill[warp];
#pragma unroll
        for (int r = 0; r < 9; r++) dst[lane + 32 * r] = src[lane + 32 * r];
    }
    __syncwarp();

    // Duplicate-pack each lane's 2x18 floats: {a,a} per channel per n per b.
    const float* vA = spill[warp] + lane * (N_DIM * CIN);
    const float* vB = vA + 576;
    ull pA0[CIN], pA1[CIN], pB0[CIN], pB1[CIN];
#pragma unroll
    for (int k = 0; k < CIN; k++) { float a = vA[k];       pA0[k] = pk2(a, a); }
#pragma unroll
    for (int k = 0; k < CIN; k++) { float a = vA[CIN + k]; pA1[k] = pk2(a, a); }
#pragma unroll
    for (int k = 0; k < CIN; k++) { float a = vB[k];       pB0[k] = pk2(a, a); }
#pragma unroll
    for (int k = 0; k < CIN; k++) { float a = vB[CIN + k]; pB1[k] = pk2(a, a); }

    const float sc0 = g_scale[2 * lane], sc1 = g_scale[2 * lane + 1];
    const float sh0 = g_shift[2 * lane], sh1 = g_shift[2 * lane + 1];
    const ull scv0 = pk2(sc0, sc0), shv0 = pk2(sh0, sh0);
    const ull scv1 = pk2(sc1, sc1), shv1 = pk2(sh1, sh1);

    float* obA = out + (size_t)b0 * (COUT * P_DIM) + lane;
    float* obB = obA + COUT * P_DIM;

#pragma unroll 2
    for (int cp = 0; cp < COUT / 2; cp++) {
        const ulonglong2* wr = (const ulonglong2*)(sW2 + cp * 10);
        const ulonglong2 w01 = wr[0], w23 = wr[1], w45 = wr[2], w67 = wr[3];
        const ull w8 = ((const ull*)wr)[8];
        ull wv[CIN] = {w01.x, w01.y, w23.x, w23.y, w45.x, w45.y, w67.x, w67.y, w8};

        ull aA0 = 0ull, aA1 = 0ull, aB0 = 0ull, aB1 = 0ull;
#pragma unroll
        for (int k = 0; k < CIN; k++) {
            asm("fma.rn.f32x2 %0,%1,%2,%0;" : "+l"(aA0) : "l"(pA0[k]), "l"(wv[k]));
            asm("fma.rn.f32x2 %0,%1,%2,%0;" : "+l"(aA1) : "l"(pA1[k]), "l"(wv[k]));
            asm("fma.rn.f32x2 %0,%1,%2,%0;" : "+l"(aB0) : "l"(pB0[k]), "l"(wv[k]));
            asm("fma.rn.f32x2 %0,%1,%2,%0;" : "+l"(aB1) : "l"(pB1[k]), "l"(wv[k]));
        }
        ull yA0, yA1, yB0, yB1;
        asm("fma.rn.f32x2 %0,%1,%2,%3;" : "=l"(yA0) : "l"(aA0), "l"(scv0), "l"(shv0));
        asm("fma.rn.f32x2 %0,%1,%2,%3;" : "=l"(yA1) : "l"(aA1), "l"(scv1), "l"(shv1));
        asm("fma.rn.f32x2 %0,%1,%2,%3;" : "=l"(yB0) : "l"(aB0), "l"(scv0), "l"(shv0));
        asm("fma.rn.f32x2 %0,%1,%2,%3;" : "=l"(yB1) : "l"(aB1), "l"(scv1), "l"(shv1));

        float a0a, a0b, a1a, a1b, b0a, b0b, b1a, b1b;
        upk2(yA0, a0a, a0b);   // channels 2cp, 2cp+1 at n=0 (row A)
        upk2(yA1, a1a, a1b);   // channels 2cp, 2cp+1 at n=1 (row A)
        upk2(yB0, b0a, b0b);
        upk2(yB1, b1a, b1b);
        obA[(2 * cp) * P_DIM]     = fmaxf(fmaxf(a0a, a1a), 0.0f);
        obA[(2 * cp + 1) * P_DIM] = fmaxf(fmaxf(a0b, a1b), 0.0f);
        obB[(2 * cp) * P_DIM]     = fmaxf(fmaxf(b0a, b1a), 0.0f);
        obB[(2 * cp + 1) * P_DIM] = fmaxf(fmaxf(b0b, b1b), 0.0f);
    }
}

// ---------------------------------------------------------------------------
extern "C" void kernel_launch(void* const* d_in, const int* in_sizes, int n_in,
                              void* d_out, int out_size) {
    const float* pillars = (const float*)d_in[0];
    // d_in[1] = num_points_per_pillar (unused by the reference computation)
    const float* W       = (const float*)d_in[2];
    const float* gamma   = (const float*)d_in[3];
    const float* beta    = (const float*)d_in[4];
    float* out           = (float*)d_out;

    k_stats<<<512, 256>>>(pillars);
    k_finalize<<<1, 256>>>(W, gamma, beta);
    k_main<<<B_TOT / 16, 256>>>(pillars, W, out);
}

// round 6
// speedup vs baseline: 1.7359x; 1.3313x over previous
#include <cuda_runtime.h>

// Problem constants (fixed by reference setup_inputs)
#define B_TOT  16384
#define P_DIM  32
#define N_DIM  2
#define CIN    9
#define COUT   64
#define PJ     64          // P*N = BatchNorm column count
#define NPAIR  45          // upper-tri pairs of 9x9
#define NSLC   8           // global accumulator slices
#define EPSV   1e-5f

typedef unsigned long long ull;

// Tiny scratch: per-slice contracted stats (zeroed by k_zero each replay)
__device__ float g_mean[NSLC][PJ];
__device__ float g_ex2[NSLC][PJ];

// ---------------------------------------------------------------------------
// f32x2 packed helpers (Blackwell sm_103a packed fp32 pipe)
// ---------------------------------------------------------------------------
__device__ __forceinline__ ull pk2(float lo, float hi) {
    ull r;
    asm("mov.b64 %0,{%1,%2};" : "=l"(r) : "f"(lo), "f"(hi));
    return r;
}
__device__ __forceinline__ void upk2(ull v, float& lo, float& hi) {
    asm("mov.b64 {%0,%1},%2;" : "=f"(lo), "=f"(hi) : "l"(v));
}

// cp.async (LDGSTS) helpers
__device__ __forceinline__ void cp16(void* s, const void* g) {
    unsigned sa = (unsigned)__cvta_generic_to_shared(s);
    asm volatile("cp.async.cg.shared.global [%0], [%1], 16;" :: "r"(sa), "l"(g));
}
#define CP_COMMIT() asm volatile("cp.async.commit_group;")
#define CP_WAIT1()  asm volatile("cp.async.wait_group 1;")
#define CP_WAIT0()  asm volatile("cp.async.wait_group 0;")

// ---------------------------------------------------------------------------
// Kernel 0: zero the 1 KB of contracted accumulators (1 block, trivial)
// ---------------------------------------------------------------------------
__global__ void k_zero() {
    const int i = threadIdx.x;           // 512 threads
    ((float*)g_mean)[i] = 0.0f;
    ((float*)g_ex2)[i]  = 0.0f;
}

// ---------------------------------------------------------------------------
// Kernel 1: per-block contracted BN stats.
//   mean_part[j] = sum_b sum_c p[b,j,c] * wsum[c]
//   ex2_part[j]  = sum_b sum_{c1<=c2} p_c1 p_c2 * G2[c1c2],  G2 = (2-[c1==c2])*W^T W
// 512 blocks x 256 threads, 4 sweeps of 8 rows, cp.async double-buffered.
// Thread (j = tid&63, g = tid>>6) consumes rows g and g+4 of each staged set.
// ---------------------------------------------------------------------------
__global__ __launch_bounds__(256) void k_stats(const float* __restrict__ pil,
                                               const float* __restrict__ W) {
    __shared__ float4 buf[2][1152];          // 2 x 8 rows x 576 floats = 36.9 KB
    __shared__ float sG2[NPAIR];
    __shared__ float swsum[CIN];
    __shared__ float smean[256];
    __shared__ float sex2[256];
    const int tid = threadIdx.x;
    const int j = tid & 63;
    const int g = tid >> 6;                  // 0..3

    // Stage sweep 0 asynchronously
    {
        const float4* src = (const float4*)(pil + (size_t)(blockIdx.x * 8) * 576);
        for (int i = tid; i < 1152; i += 256) cp16(&buf[0][i], &src[i]);
        CP_COMMIT();
    }

    // Gram (doubled off-diagonals) + column sums of W — overlaps the cp.async
    if (tid < NPAIR) {
        int c1 = 0, c2 = 0, idx = 0;
#pragma unroll
        for (int a = 0; a < CIN; a++)
#pragma unroll
            for (int b2 = a; b2 < CIN; b2++) {
                if (idx == tid) { c1 = a; c2 = b2; }
                idx++;
            }
        float s = 0.0f;
        for (int o = 0; o < COUT; o++) s += W[o * CIN + c1] * W[o * CIN + c2];
        sG2[tid] = (c1 == c2 ? 1.0f : 2.0f) * s;
    } else if (tid < NPAIR + CIN) {
        const int c = tid - NPAIR;
        float s = 0.0f;
        for (int o = 0; o < COUT; o++) s += W[o * CIN + c];
        swsum[c] = s;
    }

    float s1[CIN];
    float s2[NPAIR];
#pragma unroll
    for (int k = 0; k < CIN; k++) s1[k] = 0.0f;
#pragma unroll
    for (int k = 0; k < NPAIR; k++) s2[k] = 0.0f;

    for (int s = 0; s < 4; s++) {
        if (s < 3) {
            const float4* src =
                (const float4*)(pil + (size_t)((s + 1) * 4096 + blockIdx.x * 8) * 576);
            for (int i = tid; i < 1152; i += 256) cp16(&buf[(s + 1) & 1][i], &src[i]);
            CP_COMMIT();
            CP_WAIT1();                      // sweep s complete, s+1 may be in flight
        } else {
            CP_WAIT0();
        }
        __syncthreads();

        const float* base = (const float*)buf[s & 1];
#pragma unroll
        for (int half = 0; half < 2; half++) {
            const float* v = base + (g + 4 * half) * 576 + j * CIN;
            float vv[CIN];
#pragma unroll
            for (int k = 0; k < CIN; k++) vv[k] = v[k];
            int idx = 0;
#pragma unroll
            for (int c1 = 0; c1 < CIN; c1++) {
                s1[c1] += vv[c1];
#pragma unroll
                for (int c2 = c1; c2 < CIN; c2++) { s2[idx] += vv[c1] * vv[c2]; idx++; }
            }
        }
        __syncthreads();                     // buf[s&1] free for sweep s+2
    }

    // Per-thread contraction to two scalars (Gram data ready long ago)
    float mp = 0.0f;
#pragma unroll
    for (int k = 0; k < CIN; k++) mp += s1[k] * swsum[k];
    float ep = 0.0f;
#pragma unroll
    for (int k = 0; k < NPAIR; k++) ep += s2[k] * sG2[k];

    smean[tid] = mp;
    sex2[tid] = ep;
    __syncthreads();

    if (tid < PJ) {
        const float m = smean[tid] + smean[tid + 64] + smean[tid + 128] + smean[tid + 192];
        const float e = sex2[tid] + sex2[tid + 64] + sex2[tid + 128] + sex2[tid + 192];
        const int sl = blockIdx.x & (NSLC - 1);
        atomicAdd(&g_mean[sl][tid], m);
        atomicAdd(&g_ex2[sl][tid], e);
    }
}

// ---------------------------------------------------------------------------
// Kernel 2: main pass (absorbs BN finalize in its prologue).
// One warp per TWO consecutive b, lane = p.
//  - Prologue: threads t<64 reduce the NSLC slices (8 floats each) and form
//    scale/shift into smem; hidden under the sW2 fill + barrier.
//  - Pillar rows staged via coalesced float4; f32x2 over channel pairs with
//    padded LDS.128 weight rows shared across both b.
//  - Coalesced STG.32 per channel.
// ---------------------------------------------------------------------------
__global__ __launch_bounds__(256, 3) void k_main(const float* __restrict__ pil,
                                                 const float* __restrict__ W,
                                                 const float* __restrict__ gamma,
                                                 const float* __restrict__ beta,
                                                 float* __restrict__ out) {
    __shared__ ull sW2[(COUT / 2) * 10];        // padded {w_c,w_c+1} rows, 2.5 KB
    __shared__ float sscale[PJ];
    __shared__ float sshift[PJ];
    __shared__ float spill[8][2 * 576];         // 2 rows per warp, 36 KB
    const int tid = threadIdx.x;

    // BN finalize (per-block recompute from 4 KB of contracted stats)
    if (tid < PJ) {
        float m = 0.0f, e = 0.0f;
#pragma unroll
        for (int sl = 0; sl < NSLC; sl++) { m += g_mean[sl][tid]; e += g_ex2[sl][tid]; }
        const float inv = 1.0f / ((float)B_TOT * (float)COUT);
        m *= inv;
        e *= inv;
        const float var = e - m * m;
        const float sc = gamma[tid] * rsqrtf(var + EPSV);
        sscale[tid] = sc;
        sshift[tid] = beta[tid] - m * sc;
    }
    for (int i = tid; i < (COUT / 2) * 10; i += 256) {
        const int cp = i / 10, k = i - cp * 10;
        sW2[i] = (k < CIN) ? pk2(W[(2 * cp) * CIN + k], W[(2 * cp + 1) * CIN + k]) : 0ull;
    }
    __syncthreads();

    const int warp = tid >> 5;
    const int lane = tid & 31;
    const int b0 = (blockIdx.x * 8 + warp) * 2;     // this warp's two b

    // Coalesced stage of two pillar rows (1152 floats = 288 float4).
    {
        const float4* src = (const float4*)(pil + (size_t)b0 * 576);
        float4* dst = (float4*)spill[warp];
#pragma unroll
        for (int r = 0; r < 9; r++) dst[lane + 32 * r] = src[lane + 32 * r];
    }
    __syncwarp();

    // Duplicate-pack each lane's 2x18 floats: {a,a} per channel per n per b.
    const float* vA = spill[warp] + lane * (N_DIM * CIN);
    const float* vB = vA + 576;
    ull pA0[CIN], pA1[CIN], pB0[CIN], pB1[CIN];
#pragma unroll
    for (int k = 0; k < CIN; k++) { float a = vA[k];       pA0[k] = pk2(a, a); }
#pragma unroll
    for (int k = 0; k < CIN; k++) { float a = vA[CIN + k]; pA1[k] = pk2(a, a); }
#pragma unroll
    for (int k = 0; k < CIN; k++) { float a = vB[k];       pB0[k] = pk2(a, a); }
#pragma unroll
    for (int k = 0; k < CIN; k++) { float a = vB[CIN + k]; pB1[k] = pk2(a, a); }

    const float sc0 = sscale[2 * lane], sc1 = sscale[2 * lane + 1];
    const float sh0 = sshift[2 * lane], sh1 = sshift[2 * lane + 1];
    const ull scv0 = pk2(sc0, sc0), shv0 = pk2(sh0, sh0);
    const ull scv1 = pk2(sc1, sc1), shv1 = pk2(sh1, sh1);

    float* obA = out + (size_t)b0 * (COUT * P_DIM) + lane;
    float* obB = obA + COUT * P_DIM;

#pragma unroll 2
    for (int cp = 0; cp < COUT / 2; cp++) {
        const ulonglong2* wr = (const ulonglong2*)(sW2 + cp * 10);
        const ulonglong2 w01 = wr[0], w23 = wr[1], w45 = wr[2], w67 = wr[3];
        const ull w8 = ((const ull*)wr)[8];
        ull wv[CIN] = {w01.x, w01.y, w23.x, w23.y, w45.x, w45.y, w67.x, w67.y, w8};

        ull aA0 = 0ull, aA1 = 0ull, aB0 = 0ull, aB1 = 0ull;
#pragma unroll
        for (int k = 0; k < CIN; k++) {
            asm("fma.rn.f32x2 %0,%1,%2,%0;" : "+l"(aA0) : "l"(pA0[k]), "l"(wv[k]));
            asm("fma.rn.f32x2 %0,%1,%2,%0;" : "+l"(aA1) : "l"(pA1[k]), "l"(wv[k]));
            asm("fma.rn.f32x2 %0,%1,%2,%0;" : "+l"(aB0) : "l"(pB0[k]), "l"(wv[k]));
            asm("fma.rn.f32x2 %0,%1,%2,%0;" : "+l"(aB1) : "l"(pB1[k]), "l"(wv[k]));
        }
        ull yA0, yA1, yB0, yB1;
        asm("fma.rn.f32x2 %0,%1,%2,%3;" : "=l"(yA0) : "l"(aA0), "l"(scv0), "l"(shv0));
        asm("fma.rn.f32x2 %0,%1,%2,%3;" : "=l"(yA1) : "l"(aA1), "l"(scv1), "l"(shv1));
        asm("fma.rn.f32x2 %0,%1,%2,%3;" : "=l"(yB0) : "l"(aB0), "l"(scv0), "l"(shv0));
        asm("fma.rn.f32x2 %0,%1,%2,%3;" : "=l"(yB1) : "l"(aB1), "l"(scv1), "l"(shv1));

        float a0a, a0b, a1a, a1b, b0a, b0b, b1a, b1b;
        upk2(yA0, a0a, a0b);   // channels 2cp, 2cp+1 at n=0 (row A)
        upk2(yA1, a1a, a1b);   // channels 2cp, 2cp+1 at n=1 (row A)
        upk2(yB0, b0a, b0b);
        upk2(yB1, b1a, b1b);
        obA[(2 * cp) * P_DIM]     = fmaxf(fmaxf(a0a, a1a), 0.0f);
        obA[(2 * cp + 1) * P_DIM] = fmaxf(fmaxf(a0b, a1b), 0.0f);
        obB[(2 * cp) * P_DIM]     = fmaxf(fmaxf(b0a, b1a), 0.0f);
        obB[(2 * cp + 1) * P_DIM] = fmaxf(fmaxf(b0b, b1b), 0.0f);
    }
}

// ---------------------------------------------------------------------------
extern "C" void kernel_launch(void* const* d_in, const int* in_sizes, int n_in,
                              void* d_out, int out_size) {
    const float* pillars = (const float*)d_in[0];
    // d_in[1] = num_points_per_pillar (unused by the reference computation)
    const float* W       = (const float*)d_in[2];
    const float* gamma   = (const float*)d_in[3];
    const float* beta    = (const float*)d_in[4];
    float* out           = (float*)d_out;

    k_zero<<<1, NSLC * PJ>>>();
    k_stats<<<512, 256>>>(pillars, W);
    k_main<<<B_TOT / 16, 256>>>(pillars, W, gamma, beta, out);
}